// round 9
// baseline (speedup 1.0000x reference)
#include <cuda_runtime.h>
#include <cuda_fp16.h>
#include <cstdint>

#define NN 4096
#define IN_DIM 128
#define HD 128        // HEADS * OUT_DIM
#define HEADS 4
#define PREP_ROWS 8
#define QW 4          // warps per row (quarter each)
#define QCAP 160      // per-quarter cap (mean 15.4, sigma ~4); multiple of 16
#define ZROW NN       // sentinel row: never written -> stays zero
#define ROWS 8        // adj rows per block in the fused kernel
#define ROW_BYTES (NN * 4)   // 16 KB

// Scratch (allocation-free rule: __device__ globals; zero-init at module load)
__device__ __half g_Vh[(NN + 1) * HD];    // fp16 w*xp table + zero sentinel row
__device__ float  g_w[(NN + 1) * HEADS];  // w[j,h] + zero sentinel

// ---------------------------------------------------------------------------
// PTX helpers
// ---------------------------------------------------------------------------
__device__ __forceinline__ uint32_t smem_u32(const void* p) {
    return (uint32_t)__cvta_generic_to_shared(p);
}
__device__ __forceinline__ void mbar_init(uint32_t mbar, uint32_t count) {
    asm volatile("mbarrier.init.shared.b64 [%0], %1;" :: "r"(mbar), "r"(count) : "memory");
}
__device__ __forceinline__ void mbar_expect_tx(uint32_t mbar, uint32_t bytes) {
    asm volatile("mbarrier.arrive.expect_tx.shared.b64 _, [%0], %1;"
                 :: "r"(mbar), "r"(bytes) : "memory");
}
__device__ __forceinline__ void bulk_g2s(uint32_t dst, const void* src,
                                         uint32_t bytes, uint32_t mbar) {
    asm volatile("cp.async.bulk.shared::cta.global.mbarrier::complete_tx::bytes "
                 "[%0], [%1], %2, [%3];"
                 :: "r"(dst), "l"(src), "r"(bytes), "r"(mbar) : "memory");
}
__device__ __forceinline__ void mbar_wait(uint32_t mbar, uint32_t parity) {
    asm volatile(
        "{\n\t"
        ".reg .pred P;\n\t"
        "WL_%=:\n\t"
        "mbarrier.try_wait.parity.acquire.cta.shared::cta.b64 P, [%0], %1, 0x989680;\n\t"
        "@P bra WD_%=;\n\t"
        "bra WL_%=;\n\t"
        "WD_%=:\n\t"
        "}" :: "r"(mbar), "r"(parity) : "memory");
}

// ---------------------------------------------------------------------------
// Kernel 1: xp = x @ W ; w = exp(scale * <xp, a_j>) ; V = half(w * xp)
// ---------------------------------------------------------------------------
__global__ void __launch_bounds__(128) prep_kernel(const float* __restrict__ x,
                                                   const float* __restrict__ W,
                                                   const float* __restrict__ a) {
    int d    = threadIdx.x;
    int lane = d & 31;
    int h    = d >> 5;
    int row0 = blockIdx.x * PREP_ROWS;

    __shared__ float xs[PREP_ROWS][IN_DIM];
    {
        const float4* xg  = (const float4*)(x + (size_t)row0 * IN_DIM);
        float4*       xs4 = (float4*)xs;
        #pragma unroll
        for (int i = 0; i < PREP_ROWS * IN_DIM / 4 / 128; ++i)
            xs4[d + i * 128] = xg[d + i * 128];
    }
    float aj = a[lane];
    __syncthreads();

    float acc[PREP_ROWS];
    #pragma unroll
    for (int r = 0; r < PREP_ROWS; ++r) acc[r] = 0.f;

    const float* wcol = W + d;
    #pragma unroll
    for (int kc = 0; kc < IN_DIM; kc += 8) {
        float wv[8];
        #pragma unroll
        for (int u = 0; u < 8; ++u) wv[u] = wcol[(kc + u) * HD];
        #pragma unroll
        for (int u = 0; u < 8; ++u) {
            #pragma unroll
            for (int r = 0; r < PREP_ROWS; ++r)
                acc[r] = fmaf(xs[r][kc + u], wv[u], acc[r]);
        }
    }

    #pragma unroll
    for (int r = 0; r < PREP_ROWS; ++r) {
        float sv = acc[r] * aj;
        #pragma unroll
        for (int off = 16; off; off >>= 1)
            sv += __shfl_xor_sync(0xffffffffu, sv, off);
        float w = expf(sv * 0.17677669529663687f);   // 1/sqrt(32)
        g_Vh[(row0 + r) * HD + d] = __float2half(acc[r] * w);
        if (lane == 0) g_w[(row0 + r) * HEADS + h] = w;
    }
}

// ---------------------------------------------------------------------------
// Kernel 2 (fused, TMA-streamed): 512 blocks x 8 rows, 128 threads.
//   adj rows stream HBM->smem via cp.async.bulk, double-buffered (mbarrier).
//   Scan reads smem (LDS); ballot-free compaction; sentinel-pad to 16.
//   Gather: unroll-16 batches from L2-hot fp16 table, overlapping next TMA.
// ---------------------------------------------------------------------------
__global__ void __launch_bounds__(QW * 32) gat_kernel(const float* __restrict__ adj,
                                                      float* __restrict__ out) {
    int tid  = threadIdx.x;
    int wid  = tid >> 5;
    int lane = tid & 31;
    int h    = lane >> 3;
    int row0 = blockIdx.x * ROWS;

    __shared__ alignas(128) float buf[2][NN];        // 2 x 16 KB row buffers
    __shared__ int    s_idx[QW][QCAP];
    __shared__ float4 s_num[QW][32];
    __shared__ float  s_den[QW][32];
    __shared__ alignas(8) unsigned long long mbar_s[2];

    uint32_t mb[2] = { smem_u32(&mbar_s[0]), smem_u32(&mbar_s[1]) };

    if (tid == 0) {
        mbar_init(mb[0], 1);
        mbar_init(mb[1], 1);
    }
    __syncthreads();
    if (tid == 0) {                                  // prime the pipeline
        mbar_expect_tx(mb[0], ROW_BYTES);
        bulk_g2s(smem_u32(buf[0]), adj + (size_t)row0 * NN, ROW_BYTES, mb[0]);
        mbar_expect_tx(mb[1], ROW_BYTES);
        bulk_g2s(smem_u32(buf[1]), adj + (size_t)(row0 + 1) * NN, ROW_BYTES, mb[1]);
    }

    for (int r = 0; r < ROWS; ++r) {
        int b  = r & 1;
        int ph = (r >> 1) & 1;                       // phase flips per reuse
        mbar_wait(mb[b], ph);

        // ---- scan quarter from smem (LDS.128, cheap) ----
        const float4* q = (const float4*)buf[b];
        float4 v[8];
        #pragma unroll
        for (int c = 0; c < 8; ++c)
            v[c] = q[wid * 256 + c * 32 + lane];

        unsigned mask = 0u;
        #pragma unroll
        for (int c = 0; c < 8; ++c) {
            mask |= (v[c].x != 0.f ? 1u : 0u) << (4 * c);
            mask |= (v[c].y != 0.f ? 1u : 0u) << (4 * c + 1);
            mask |= (v[c].z != 0.f ? 1u : 0u) << (4 * c + 2);
            mask |= (v[c].w != 0.f ? 1u : 0u) << (4 * c + 3);
        }
        int cntl = __popc(mask);

        int inc = cntl;                              // warp inclusive scan
        #pragma unroll
        for (int off = 1; off < 32; off <<= 1) {
            int nb = __shfl_up_sync(0xffffffffu, inc, off);
            if (lane >= off) inc += nb;
        }
        int base  = inc - cntl;
        int total = __shfl_sync(0xffffffffu, inc, 31);
        total = min(total, QCAP);

        int* my = s_idx[wid];
        int colb = 4 * (wid * 256 + lane);
        while (mask) {
            int bb = __ffs(mask) - 1; mask &= mask - 1;
            int col = colb + 128 * (bb >> 2) + (bb & 3);
            if (base < QCAP) my[base] = col;
            ++base;
        }
        int padded = (total + 15) & ~15;
        if (lane < padded - total) my[total + lane] = ZROW;
        __syncthreads();                             // buf[b] fully consumed

        // ---- refill buf[b] with row r+2 while we gather ----
        if (tid == 0 && r + 2 < ROWS) {
            mbar_expect_tx(mb[b], ROW_BYTES);
            bulk_g2s(smem_u32(buf[b]), adj + (size_t)(row0 + r + 2) * NN,
                     ROW_BYTES, mb[b]);
        }

        // ---- gather: unroll-16 batches only (sentinel-padded) ----
        const uint2* Vh2 = (const uint2*)g_Vh;       // row stride 32 uint2
        float4 num = make_float4(0.f, 0.f, 0.f, 0.f);
        float  den = 0.f;

        for (int t = 0; t < padded; t += 16) {
            uint2 pv[16];
            float ww[16];
            #pragma unroll
            for (int u = 0; u < 16; ++u) {
                int j = my[t + u];
                pv[u] = Vh2[j * 32 + lane];
                ww[u] = g_w[j * HEADS + h];
            }
            #pragma unroll
            for (int u = 0; u < 16; ++u) {
                float2 lo = __half22float2(*(const __half2*)&pv[u].x);
                float2 hi = __half22float2(*(const __half2*)&pv[u].y);
                num.x += lo.x; num.y += lo.y; num.z += hi.x; num.w += hi.y;
                den   += ww[u];
            }
        }

        // ---- combine quarter partials (fixed order -> deterministic) ----
        s_num[wid][lane] = num;
        s_den[wid][lane] = den;
        __syncthreads();

        if (wid == 0) {
            float4 n0 = s_num[0][lane], n1 = s_num[1][lane];
            float4 n2 = s_num[2][lane], n3 = s_num[3][lane];
            float dsum = ((s_den[0][lane] + s_den[1][lane]) +
                          (s_den[2][lane] + s_den[3][lane]));
            float4 o;
            o.x = ((n0.x + n1.x) + (n2.x + n3.x)) / dsum;
            o.y = ((n0.y + n1.y) + (n2.y + n3.y)) / dsum;
            o.z = ((n0.z + n1.z) + (n2.z + n3.z)) / dsum;
            o.w = ((n0.w + n1.w) + (n2.w + n3.w)) / dsum;
            ((float4*)out)[(size_t)(row0 + r) * 32 + lane] = o;
        }
        __syncthreads();                             // protect s_num/s_idx reuse
    }
}

extern "C" void kernel_launch(void* const* d_in, const int* in_sizes, int n_in,
                              void* d_out, int out_size) {
    const float* x   = (const float*)d_in[0];   // [4096, 128]
    const float* adj = (const float*)d_in[1];   // [4096, 4096]
    const float* W   = (const float*)d_in[2];   // [128, 128]
    const float* a   = (const float*)d_in[3];   // [64]
    float* out = (float*)d_out;                 // [4096, 128]

    prep_kernel<<<NN / PREP_ROWS, 128>>>(x, W, a);
    gat_kernel<<<NN / ROWS, QW * 32>>>(adj, out);
}

// round 11
// speedup vs baseline: 1.1202x; 1.1202x over previous
#include <cuda_runtime.h>
#include <cuda_fp16.h>
#include <cstdint>

#define NN 4096
#define IN_DIM 128
#define HD 128        // HEADS * OUT_DIM
#define HEADS 4
#define PREP_ROWS 8
#define QW 4          // warps per row (quarter each)
#define QCAP 160      // per-quarter cap (mean 15.4, sigma ~4); multiple of 16
#define ZROW NN       // sentinel row: never written -> stays zero
#define ROWS 4        // adj rows per block (grid 1024 -> ~full residency)

// Scratch (allocation-free rule: __device__ globals; zero-init at module load)
__device__ __half g_Vh[(NN + 1) * HD];    // fp16 w*xp table + zero sentinel row
__device__ float  g_w[(NN + 1) * HEADS];  // w[j,h] + zero sentinel

__device__ __forceinline__ uint32_t smem_u32(const void* p) {
    return (uint32_t)__cvta_generic_to_shared(p);
}

// ---------------------------------------------------------------------------
// Kernel 1: xp = x @ W ; w = exp(scale * <xp, a_j>) ; V = half(w * xp)
// ---------------------------------------------------------------------------
__global__ void __launch_bounds__(128) prep_kernel(const float* __restrict__ x,
                                                   const float* __restrict__ W,
                                                   const float* __restrict__ a) {
    int d    = threadIdx.x;
    int lane = d & 31;
    int h    = d >> 5;
    int row0 = blockIdx.x * PREP_ROWS;

    __shared__ float xs[PREP_ROWS][IN_DIM];
    {
        const float4* xg  = (const float4*)(x + (size_t)row0 * IN_DIM);
        float4*       xs4 = (float4*)xs;
        #pragma unroll
        for (int i = 0; i < PREP_ROWS * IN_DIM / 4 / 128; ++i)
            xs4[d + i * 128] = xg[d + i * 128];
    }
    float aj = a[lane];
    __syncthreads();

    float acc[PREP_ROWS];
    #pragma unroll
    for (int r = 0; r < PREP_ROWS; ++r) acc[r] = 0.f;

    const float* wcol = W + d;
    #pragma unroll
    for (int kc = 0; kc < IN_DIM; kc += 8) {
        float wv[8];
        #pragma unroll
        for (int u = 0; u < 8; ++u) wv[u] = wcol[(kc + u) * HD];
        #pragma unroll
        for (int u = 0; u < 8; ++u) {
            #pragma unroll
            for (int r = 0; r < PREP_ROWS; ++r)
                acc[r] = fmaf(xs[r][kc + u], wv[u], acc[r]);
        }
    }

    #pragma unroll
    for (int r = 0; r < PREP_ROWS; ++r) {
        float sv = acc[r] * aj;
        #pragma unroll
        for (int off = 16; off; off >>= 1)
            sv += __shfl_xor_sync(0xffffffffu, sv, off);
        float w = expf(sv * 0.17677669529663687f);   // 1/sqrt(32)
        g_Vh[(row0 + r) * HD + d] = __float2half(acc[r] * w);
        if (lane == 0) g_w[(row0 + r) * HEADS + h] = w;
    }
}

// ---------------------------------------------------------------------------
// Kernel 2 (fused, cp.async-pipelined): 1024 blocks x 4 rows, 128 threads.
// Row stream HBM->smem via LDGSTS double buffer (zero register cost), so the
// DRAM stream overlaps scan+gather fully. Scan from smem (LDS), ballot-free
// compaction, sentinel-padded unroll-16 gather from L2-hot fp16 table.
// Tail fix: wait_group depth 0 on the LAST row (only its own group pending).
// ---------------------------------------------------------------------------
__global__ void __launch_bounds__(QW * 32) gat_kernel(const float* __restrict__ adj,
                                                      float* __restrict__ out) {
    int tid  = threadIdx.x;
    int wid  = tid >> 5;
    int lane = tid & 31;
    int h    = lane >> 3;
    int row0 = blockIdx.x * ROWS;

    __shared__ alignas(16) float buf[2][NN];   // 2 x 16 KB row buffers
    __shared__ int    s_idx[QW][QCAP];
    __shared__ float4 s_num[QW][32];
    __shared__ float  s_den[QW][32];

    // issue one full row (16 KB) as 8 lane-contiguous cp.async.cg per thread
    auto issue_row = [&](int r, int b) {
        const float4* src = (const float4*)(adj + (size_t)(row0 + r) * NN);
        uint32_t dst = smem_u32(&buf[b][0]);
        #pragma unroll
        for (int u = 0; u < 8; ++u) {
            int idx = u * 128 + tid;           // warp-contiguous 512B segments
            asm volatile("cp.async.cg.shared.global [%0], [%1], 16;"
                         :: "r"(dst + idx * 16), "l"(src + idx) : "memory");
        }
        asm volatile("cp.async.commit_group;" ::: "memory");
    };

    issue_row(0, 0);
    issue_row(1, 1);

    #pragma unroll
    for (int r = 0; r < ROWS; ++r) {
        int b = r & 1;
        // Row r's group must be complete. Groups commit in row order; after
        // iteration r, (r+1 .. min(r+1, ROWS-1)) may stay in flight.
        if (r == ROWS - 1)
            asm volatile("cp.async.wait_group 0;" ::: "memory");
        else
            asm volatile("cp.async.wait_group 1;" ::: "memory");
        __syncthreads();

        // ---- scan quarter from smem ----
        const float4* q = (const float4*)buf[b];
        float4 v[8];
        #pragma unroll
        for (int c = 0; c < 8; ++c)
            v[c] = q[wid * 256 + c * 32 + lane];
        __syncthreads();                       // buf[b] consumed -> refillable

        if (r + 2 < ROWS) issue_row(r + 2, b); // stream next while we process

        unsigned mask = 0u;
        #pragma unroll
        for (int c = 0; c < 8; ++c) {
            mask |= (v[c].x != 0.f ? 1u : 0u) << (4 * c);
            mask |= (v[c].y != 0.f ? 1u : 0u) << (4 * c + 1);
            mask |= (v[c].z != 0.f ? 1u : 0u) << (4 * c + 2);
            mask |= (v[c].w != 0.f ? 1u : 0u) << (4 * c + 3);
        }
        int cntl = __popc(mask);

        int inc = cntl;                        // warp inclusive scan
        #pragma unroll
        for (int off = 1; off < 32; off <<= 1) {
            int nb = __shfl_up_sync(0xffffffffu, inc, off);
            if (lane >= off) inc += nb;
        }
        int base  = inc - cntl;
        int total = __shfl_sync(0xffffffffu, inc, 31);
        total = min(total, QCAP);

        int* my = s_idx[wid];
        int colb = 4 * (wid * 256 + lane);
        while (mask) {                         // ~0.5 iters/lane avg
            int bb = __ffs(mask) - 1; mask &= mask - 1;
            int col = colb + 128 * (bb >> 2) + (bb & 3);
            if (base < QCAP) my[base] = col;
            ++base;
        }
        int padded = (total + 15) & ~15;
        if (lane < padded - total) my[total + lane] = ZROW;
        __syncwarp();

        // ---- gather: unroll-16 batches only (sentinel-padded) ----
        const uint2* Vh2 = (const uint2*)g_Vh; // row stride 32 uint2
        float4 num = make_float4(0.f, 0.f, 0.f, 0.f);
        float  den = 0.f;

        for (int t = 0; t < padded; t += 16) {
            uint2 pv[16];
            float ww[16];
            #pragma unroll
            for (int u = 0; u < 16; ++u) {
                int j = my[t + u];
                pv[u] = Vh2[j * 32 + lane];
                ww[u] = g_w[j * HEADS + h];
            }
            #pragma unroll
            for (int u = 0; u < 16; ++u) {
                float2 lo = __half22float2(*(const __half2*)&pv[u].x);
                float2 hi = __half22float2(*(const __half2*)&pv[u].y);
                num.x += lo.x; num.y += lo.y; num.z += hi.x; num.w += hi.y;
                den   += ww[u];
            }
        }

        // ---- combine quarter partials (fixed order -> deterministic) ----
        s_num[wid][lane] = num;
        s_den[wid][lane] = den;
        __syncthreads();

        if (wid == 0) {
            float4 n0 = s_num[0][lane], n1 = s_num[1][lane];
            float4 n2 = s_num[2][lane], n3 = s_num[3][lane];
            float dsum = ((s_den[0][lane] + s_den[1][lane]) +
                          (s_den[2][lane] + s_den[3][lane]));
            float4 o;
            o.x = ((n0.x + n1.x) + (n2.x + n3.x)) / dsum;
            o.y = ((n0.y + n1.y) + (n2.y + n3.y)) / dsum;
            o.z = ((n0.z + n1.z) + (n2.z + n3.z)) / dsum;
            o.w = ((n0.w + n1.w) + (n2.w + n3.w)) / dsum;
            ((float4*)out)[(size_t)(row0 + r) * 32 + lane] = o;
        }
        __syncthreads();                       // protect s_idx/s_num reuse
    }
}

extern "C" void kernel_launch(void* const* d_in, const int* in_sizes, int n_in,
                              void* d_out, int out_size) {
    const float* x   = (const float*)d_in[0];   // [4096, 128]
    const float* adj = (const float*)d_in[1];   // [4096, 4096]
    const float* W   = (const float*)d_in[2];   // [128, 128]
    const float* a   = (const float*)d_in[3];   // [64]
    float* out = (float*)d_out;                 // [4096, 128]

    prep_kernel<<<NN / PREP_ROWS, 128>>>(x, W, a);
    gat_kernel<<<NN / ROWS, QW * 32>>>(adj, out);
}

// round 12
// speedup vs baseline: 1.1486x; 1.0253x over previous
#include <cuda_runtime.h>
#include <cuda_fp16.h>

#define NN 4096
#define IN_DIM 128
#define HD 128        // HEADS * OUT_DIM
#define HEADS 4
#define PREP_ROWS 8
#define QW 4          // warps per row (quarter each)
#define QCAP 160      // per-quarter cap (mean 15.4, sigma ~4); multiple of 16
#define ZROW NN       // sentinel row: never written -> stays zero
#define RPB 2         // rows per block (software-pipelined)

// Scratch (allocation-free rule: __device__ globals; zero-init at module load)
__device__ __half g_Vh[(NN + 1) * HD];    // fp16 w*xp table + zero sentinel row
__device__ float  g_w[(NN + 1) * HEADS];  // w[j,h] + zero sentinel

// ---------------------------------------------------------------------------
// Kernel 1: xp = x @ W ; w = exp(scale * <xp, a_j>) ; V = half(w * xp)
// ---------------------------------------------------------------------------
__global__ void __launch_bounds__(128) prep_kernel(const float* __restrict__ x,
                                                   const float* __restrict__ W,
                                                   const float* __restrict__ a) {
    int d    = threadIdx.x;
    int lane = d & 31;
    int h    = d >> 5;
    int row0 = blockIdx.x * PREP_ROWS;

    __shared__ float xs[PREP_ROWS][IN_DIM];
    {
        const float4* xg  = (const float4*)(x + (size_t)row0 * IN_DIM);
        float4*       xs4 = (float4*)xs;
        #pragma unroll
        for (int i = 0; i < PREP_ROWS * IN_DIM / 4 / 128; ++i)
            xs4[d + i * 128] = xg[d + i * 128];
    }
    float aj = a[lane];
    __syncthreads();

    float acc[PREP_ROWS];
    #pragma unroll
    for (int r = 0; r < PREP_ROWS; ++r) acc[r] = 0.f;

    const float* wcol = W + d;
    #pragma unroll
    for (int kc = 0; kc < IN_DIM; kc += 8) {
        float wv[8];
        #pragma unroll
        for (int u = 0; u < 8; ++u) wv[u] = wcol[(kc + u) * HD];
        #pragma unroll
        for (int u = 0; u < 8; ++u) {
            #pragma unroll
            for (int r = 0; r < PREP_ROWS; ++r)
                acc[r] = fmaf(xs[r][kc + u], wv[u], acc[r]);
        }
    }

    #pragma unroll
    for (int r = 0; r < PREP_ROWS; ++r) {
        float sv = acc[r] * aj;
        #pragma unroll
        for (int off = 16; off; off >>= 1)
            sv += __shfl_xor_sync(0xffffffffu, sv, off);
        float w = expf(sv * 0.17677669529663687f);   // 1/sqrt(32)
        g_Vh[(row0 + r) * HD + d] = __float2half(acc[r] * w);
        if (lane == 0) g_w[(row0 + r) * HEADS + h] = w;
    }
}

// ---------------------------------------------------------------------------
// Kernel 2: block per 2 rows, warp per quarter. __launch_bounds__(128, 4)
// gives ptxas ~128 regs/thread so the 8-float4 adj burst stays register-
// resident (true MLP=8). Software pipeline: burst0 -> scan0 -> issue burst1
// -> gather0 -> out0 -> scan1 -> gather1 -> out1, so row1's DRAM burst hides
// under row0's gather. __ldcs streams adj past L2 (V/w tables stay hot).
// ---------------------------------------------------------------------------
struct QuarterState {
    int padded;
};

__device__ __forceinline__ int scan_compact(const float4 v[8], int* my,
                                            int wid, int lane) {
    unsigned mask = 0u;
    #pragma unroll
    for (int c = 0; c < 8; ++c) {
        mask |= (v[c].x != 0.f ? 1u : 0u) << (4 * c);
        mask |= (v[c].y != 0.f ? 1u : 0u) << (4 * c + 1);
        mask |= (v[c].z != 0.f ? 1u : 0u) << (4 * c + 2);
        mask |= (v[c].w != 0.f ? 1u : 0u) << (4 * c + 3);
    }
    int cntl = __popc(mask);

    int inc = cntl;                              // warp inclusive scan
    #pragma unroll
    for (int off = 1; off < 32; off <<= 1) {
        int nb = __shfl_up_sync(0xffffffffu, inc, off);
        if (lane >= off) inc += nb;
    }
    int base  = inc - cntl;
    int total = __shfl_sync(0xffffffffu, inc, 31);
    total = min(total, QCAP);

    int colb = 4 * (wid * 256 + lane);
    while (mask) {                               // ~0.5 iters/lane avg
        int b = __ffs(mask) - 1; mask &= mask - 1;
        int col = colb + 128 * (b >> 2) + (b & 3);
        if (base < QCAP) my[base] = col;
        ++base;
    }
    int padded = (total + 15) & ~15;
    if (lane < padded - total) my[total + lane] = ZROW;
    __syncwarp();
    return padded;
}

__device__ __forceinline__ void gather_acc(const int* my, int padded, int lane,
                                           int h, float4& num, float& den) {
    const uint2* Vh2 = (const uint2*)g_Vh;       // row stride 32 uint2
    num = make_float4(0.f, 0.f, 0.f, 0.f);
    den = 0.f;
    for (int t = 0; t < padded; t += 16) {       // 32 loads in flight
        uint2 pv[16];
        float ww[16];
        #pragma unroll
        for (int u = 0; u < 16; ++u) {
            int j = my[t + u];
            pv[u] = Vh2[j * 32 + lane];
            ww[u] = g_w[j * HEADS + h];
        }
        #pragma unroll
        for (int u = 0; u < 16; ++u) {
            float2 lo = __half22float2(*(const __half2*)&pv[u].x);
            float2 hi = __half22float2(*(const __half2*)&pv[u].y);
            num.x += lo.x; num.y += lo.y; num.z += hi.x; num.w += hi.y;
            den   += ww[u];
        }
    }
}

__global__ void __launch_bounds__(QW * 32, 4) gat_kernel(const float* __restrict__ adj,
                                                         float* __restrict__ out) {
    int tid  = threadIdx.x;
    int wid  = tid >> 5;
    int lane = tid & 31;
    int h    = lane >> 3;
    int row0 = blockIdx.x * RPB;

    __shared__ int    s_idx[QW][QCAP];
    __shared__ float4 s_num[QW][32];
    __shared__ float  s_den[QW][32];

    const float4* ar0 = (const float4*)(adj + (size_t)row0 * NN);
    const float4* ar1 = (const float4*)(adj + (size_t)(row0 + 1) * NN);
    int qbase = wid * 256 + lane;

    // ---- burst 0: 8 LDG.128 (streaming) front-batched ----
    float4 v0[8];
    #pragma unroll
    for (int c = 0; c < 8; ++c) v0[c] = __ldcs(&ar0[qbase + c * 32]);

    // ---- scan row0 (uses v0, frees it) ----
    int* my = s_idx[wid];
    int padded0 = scan_compact(v0, my, wid, lane);

    // ---- burst 1 issued NOW: overlaps row0's gather ----
    float4 v1[8];
    #pragma unroll
    for (int c = 0; c < 8; ++c) v1[c] = __ldcs(&ar1[qbase + c * 32]);

    // ---- gather row0 ----
    float4 num; float den;
    gather_acc(my, padded0, lane, h, num, den);

    s_num[wid][lane] = num;
    s_den[wid][lane] = den;
    __syncthreads();
    if (wid == 0) {
        float4 n0 = s_num[0][lane], n1 = s_num[1][lane];
        float4 n2 = s_num[2][lane], n3 = s_num[3][lane];
        float dsum = ((s_den[0][lane] + s_den[1][lane]) +
                      (s_den[2][lane] + s_den[3][lane]));
        float4 o;
        o.x = ((n0.x + n1.x) + (n2.x + n3.x)) / dsum;
        o.y = ((n0.y + n1.y) + (n2.y + n3.y)) / dsum;
        o.z = ((n0.z + n1.z) + (n2.z + n3.z)) / dsum;
        o.w = ((n0.w + n1.w) + (n2.w + n3.w)) / dsum;
        ((float4*)out)[(size_t)row0 * 32 + lane] = o;
    }
    __syncthreads();                             // s_num reuse for row1

    // ---- row 1: scan + gather (burst long since landed) ----
    int padded1 = scan_compact(v1, my, wid, lane);
    gather_acc(my, padded1, lane, h, num, den);

    s_num[wid][lane] = num;
    s_den[wid][lane] = den;
    __syncthreads();
    if (wid == 0) {
        float4 n0 = s_num[0][lane], n1 = s_num[1][lane];
        float4 n2 = s_num[2][lane], n3 = s_num[3][lane];
        float dsum = ((s_den[0][lane] + s_den[1][lane]) +
                      (s_den[2][lane] + s_den[3][lane]));
        float4 o;
        o.x = ((n0.x + n1.x) + (n2.x + n3.x)) / dsum;
        o.y = ((n0.y + n1.y) + (n2.y + n3.y)) / dsum;
        o.z = ((n0.z + n1.z) + (n2.z + n3.z)) / dsum;
        o.w = ((n0.w + n1.w) + (n2.w + n3.w)) / dsum;
        ((float4*)out)[(size_t)(row0 + 1) * 32 + lane] = o;
    }
}

extern "C" void kernel_launch(void* const* d_in, const int* in_sizes, int n_in,
                              void* d_out, int out_size) {
    const float* x   = (const float*)d_in[0];   // [4096, 128]
    const float* adj = (const float*)d_in[1];   // [4096, 4096]
    const float* W   = (const float*)d_in[2];   // [128, 128]
    const float* a   = (const float*)d_in[3];   // [64]
    float* out = (float*)d_out;                 // [4096, 128]

    prep_kernel<<<NN / PREP_ROWS, 128>>>(x, W, a);
    gat_kernel<<<NN / RPB, QW * 32>>>(adj, out);
}